// round 11
// baseline (speedup 1.0000x reference)
#include <cuda_runtime.h>

// ---------------------------------------------------------------------------
// Routing_2259152797848: capsule routing
// R11 = R10 k_route VERBATIM (best: 268.4us total)
//       + k_fc rebuilt on packed fma.rn.f32x2 (row-pair accumulators)
//       + k_init folded into k_fc block 0 (one fewer launch).
// ---------------------------------------------------------------------------

#define MAXN 50016
#define D    128
#define CH   8
#define KD   16
#define M    32

typedef unsigned long long u64;

__device__ float g_z[(size_t)(MAXN + 1) * D];
__device__ int   g_is64;

__device__ __forceinline__ u64 pk(float a, float b) {
    u64 r; asm("mov.b64 %0,{%1,%2};" : "=l"(r) : "f"(a), "f"(b)); return r;
}
__device__ __forceinline__ u64 pk1(float a) {           // (a, a)
    u64 r; asm("mov.b64 %0,{%1,%1};" : "=l"(r) : "f"(a)); return r;
}
__device__ __forceinline__ float plo(u64 v) {
    float a; asm("{.reg .f32 h; mov.b64 {%0,h}, %1;}" : "=f"(a) : "l"(v)); return a;
}
__device__ __forceinline__ float phi(u64 v) {
    float b; asm("{.reg .f32 l; mov.b64 {l,%0}, %1;}" : "=f"(b) : "l"(v)); return b;
}
__device__ __forceinline__ u64 fma2(u64 a, u64 b, u64 c) {
    u64 r; asm("fma.rn.f32x2 %0,%1,%2,%3;" : "=l"(r) : "l"(a), "l"(b), "l"(c)); return r;
}

// --- FC + relu + per-capsule normalize, packed f32x2 row pairs -----------------
// Block: 128 threads, 32 rows. Accumulator acc2[pr][cc] packs rows
// (ty+4pr, ty+4pr+16) for column tx+32cc. W duplicated per-scalar via mov.b64;
// x pre-paired in SMEM xp[pair][k] (u64, stride 132: conflict-free fill,
// broadcast reads). Block 0 additionally zeroes the pad row and sniffs the
// neighbor_id element width (int64 ids in [0,n] have all odd words zero).
__global__ void k_fc(const float* __restrict__ x, const float* __restrict__ W,
                     const float* __restrict__ b, const int* __restrict__ nidw,
                     int n) {
    extern __shared__ float smem[];
    float* w_s = smem;                        // [128][132]
    u64*   xp  = (u64*)(smem + 128 * 132);    // [16][132] u64

    const int t = threadIdx.x;
    const int r0 = blockIdx.x * 32;

    // folded init (block 0 only)
    if (blockIdx.x == 0) {
        g_z[(size_t)n * D + t] = 0.0f;        // 128 threads cover pad row
        if (t < 32) {
            int any = 0;
            #pragma unroll
            for (int i = 0; i < 4; i++) any |= nidw[2 * (t * 4 + i) + 1];
            unsigned msk = __ballot_sync(0xffffffffu, any != 0);
            if (t == 0) g_is64 = (msk == 0) ? 1 : 0;
        }
    }

    // load W (4096 float4), padded rows of 33 float4
    const float4* W4 = (const float4*)W;
    float4* ws4 = (float4*)w_s;
    #pragma unroll
    for (int i = 0; i < 32; i++) {
        int idx4 = t + 128 * i;
        int j = idx4 >> 5, kk = idx4 & 31;
        ws4[j * 33 + kk] = W4[idx4];
    }
    // load x into paired layout: xp[p*132 + k] = (x[r0+p][k], x[r0+p+16][k])
    #pragma unroll
    for (int p = 0; p < 16; p++) {
        float lo = 0.f, hi = 0.f;
        if (r0 + p      < n) lo = x[(size_t)(r0 + p)      * D + t];
        if (r0 + p + 16 < n) hi = x[(size_t)(r0 + p + 16) * D + t];
        xp[p * 132 + t] = pk(lo, hi);
    }
    __syncthreads();

    const int tx = t & 31;
    const int ty = t >> 5;

    u64 acc2[4][4];
    #pragma unroll
    for (int pr = 0; pr < 4; pr++)
        #pragma unroll
        for (int cc = 0; cc < 4; cc++) acc2[pr][cc] = pk(0.f, 0.f);

    #pragma unroll 4
    for (int k4 = 0; k4 < 32; k4++) {
        float4 wv[4];
        #pragma unroll
        for (int cc = 0; cc < 4; cc++) wv[cc] = ws4[(tx + 32 * cc) * 33 + k4];
        #pragma unroll
        for (int j = 0; j < 4; j++) {
            int k = 4 * k4 + j;
            u64 xq[4];
            #pragma unroll
            for (int pr = 0; pr < 4; pr++)
                xq[pr] = xp[(ty + 4 * pr) * 132 + k];   // broadcast LDS.64
            #pragma unroll
            for (int cc = 0; cc < 4; cc++) {
                float w = (j == 0) ? wv[cc].x : (j == 1) ? wv[cc].y
                        : (j == 2) ? wv[cc].z : wv[cc].w;
                u64 w2 = pk1(w);
                #pragma unroll
                for (int pr = 0; pr < 4; pr++)
                    acc2[pr][cc] = fma2(xq[pr], w2, acc2[pr][cc]);
            }
        }
    }

    float bv[4];
    #pragma unroll
    for (int cc = 0; cc < 4; cc++) bv[cc] = b[tx + 32 * cc];

    // relu + bias + per-capsule (16-col) normalize; shfl group = 16 lanes
    #pragma unroll
    for (int pr = 0; pr < 4; pr++) {
        #pragma unroll
        for (int h = 0; h < 2; h++) {
            int row = r0 + ty + 4 * pr + 16 * h;
            #pragma unroll
            for (int cc = 0; cc < 4; cc++) {
                float raw = h ? phi(acc2[pr][cc]) : plo(acc2[pr][cc]);
                float v = fmaxf(raw + bv[cc], 0.f);
                float s = v * v;
                s += __shfl_xor_sync(0xffffffffu, s, 1);
                s += __shfl_xor_sync(0xffffffffu, s, 2);
                s += __shfl_xor_sync(0xffffffffu, s, 4);
                s += __shfl_xor_sync(0xffffffffu, s, 8);
                float inv = rsqrtf(fmaxf(s, 1e-24f));
                if (row < n) g_z[(size_t)row * D + tx + 32 * cc] = v * inv;
            }
        }
    }
}

// --- routing: 256 threads = 2 independent nodes (R4/R10 VERBATIM) --------------
__global__ __launch_bounds__(256) void k_route(const void* __restrict__ nid_raw,
                                               float* __restrict__ out, int n) {
    __shared__ float d_s[2][M * 9];          // d_s[grp][m*9+c]
    __shared__ __align__(16) float ps[2][CH * 36];  // ps[grp][c*36+m]
    __shared__ int ids[2][M];

    const int t   = threadIdx.x;
    const int grp = t >> 7;                  // node group 0/1
    const int tl  = t & 127;
    const int bid = 1 + grp;                 // named barrier id (warp-uniform)
    const int node = blockIdx.x * 2 + grp;
    if (node >= n) return;                   // whole 128-group exits together
    const int is64 = g_is64;

    if (tl < M) {
        long long id;
        if (is64) id = ((const long long*)nid_raw)[(size_t)node * M + tl];
        else      id = (long long)((const int*)nid_raw)[(size_t)node * M + tl];
        ids[grp][tl] = (int)id;
    }
    const float xc = g_z[(size_t)node * D + tl];
    asm volatile("bar.sync %0, %1;" :: "r"(bid), "r"(128) : "memory");

    // coalesced gather: one (c,k) column of all 32 neighbor rows
    float nbr[M];
    #pragma unroll
    for (int m = 0; m < M; m++)
        nbr[m] = g_z[(size_t)ids[grp][m] * D + tl];

    const int cB = tl >> 4;          // channel (tree / phase B)
    const int g  = tl & 15;          // lane within 16-lane channel group
    const int m0 = tl >> 3;          // softmax identity
    const int cA = tl & 7;
    const int mbase = ((g & 1) << 4) | ((g & 2) << 2) | (g & 4) | ((g >> 3) << 1);

    float u_val = xc;
    float acc;

    for (int it = 0; it < 3; it++) {
        // ---- tree: d[m] = sum_k u[c,k]*nb[m,c,k], split over 16 lanes ----
        float s1[16];
        #pragma unroll
        for (int i = 0; i < 16; i++) {
            float lo = u_val * nbr[i];
            float hi = u_val * nbr[i + 16];
            float keep = (g & 1) ? hi : lo;
            float send = (g & 1) ? lo : hi;
            s1[i] = keep + __shfl_xor_sync(0xffffffffu, send, 1);
        }
        float s2[8];
        #pragma unroll
        for (int i = 0; i < 8; i++) {
            float keep = (g & 2) ? s1[i + 8] : s1[i];
            float send = (g & 2) ? s1[i] : s1[i + 8];
            s2[i] = keep + __shfl_xor_sync(0xffffffffu, send, 2);
        }
        float s3[4];
        #pragma unroll
        for (int i = 0; i < 4; i++) {
            float keep = (g & 4) ? s2[i + 4] : s2[i];
            float send = (g & 4) ? s2[i] : s2[i + 4];
            s3[i] = keep + __shfl_xor_sync(0xffffffffu, send, 4);
        }
        float s4[2];
        #pragma unroll
        for (int i = 0; i < 2; i++) {
            float keep = (g & 8) ? s3[i + 2] : s3[i];
            float send = (g & 8) ? s3[i] : s3[i + 2];
            s4[i] = keep + __shfl_xor_sync(0xffffffffu, send, 8);
        }
        // |d| <= 1 (unit capsules): exp safe without max-subtraction
        d_s[grp][(mbase + 0) * 9 + cB] = __expf(s4[0]);
        d_s[grp][(mbase + 1) * 9 + cB] = __expf(s4[1]);
        asm volatile("bar.sync %0, %1;" :: "r"(bid), "r"(128) : "memory");

        // ---- softmax over c (8 adjacent lanes), thread = (m0, cA) ----
        float e0 = d_s[grp][m0 * 9 + cA];
        float e1 = d_s[grp][(m0 + 16) * 9 + cA];
        float sm0 = e0, sm1 = e1;
        sm0 += __shfl_xor_sync(0xffffffffu, sm0, 1);
        sm1 += __shfl_xor_sync(0xffffffffu, sm1, 1);
        sm0 += __shfl_xor_sync(0xffffffffu, sm0, 2);
        sm1 += __shfl_xor_sync(0xffffffffu, sm1, 2);
        sm0 += __shfl_xor_sync(0xffffffffu, sm0, 4);
        sm1 += __shfl_xor_sync(0xffffffffu, sm1, 4);
        ps[grp][cA * 36 + m0]      = __fdividef(e0, sm0);
        ps[grp][cA * 36 + m0 + 16] = __fdividef(e1, sm1);
        asm volatile("bar.sync %0, %1;" :: "r"(bid), "r"(128) : "memory");

        // ---- phase B: u[c,k] = x_caps + sum_m p[m,c]*nb[m,c,k] ----
        acc = xc;
        #pragma unroll
        for (int j = 0; j < 8; j++) {
            float4 p = *(const float4*)&ps[grp][cB * 36 + 4 * j];
            acc = fmaf(p.x, nbr[4 * j + 0], acc);
            acc = fmaf(p.y, nbr[4 * j + 1], acc);
            acc = fmaf(p.z, nbr[4 * j + 2], acc);
            acc = fmaf(p.w, nbr[4 * j + 3], acc);
        }

        if (it < 2) {
            float sq = acc * acc;
            sq += __shfl_xor_sync(0xffffffffu, sq, 1);
            sq += __shfl_xor_sync(0xffffffffu, sq, 2);
            sq += __shfl_xor_sync(0xffffffffu, sq, 4);
            sq += __shfl_xor_sync(0xffffffffu, sq, 8);
            u_val = acc * rsqrtf(fmaxf(sq, 1e-24f));
        } else {
            out[(size_t)node * D + tl] = acc;
        }
    }
}

// ---------------------------------------------------------------------------
extern "C" void kernel_launch(void* const* d_in, const int* in_sizes, int n_in,
                              void* d_out, int out_size) {
    const float* x = (const float*)d_in[0];
    const float* W = (const float*)d_in[1];
    const float* b = (const float*)d_in[2];
    const void*  nid = d_in[3];
    float* out = (float*)d_out;

    int n = in_sizes[0] / D;

    // W smem [128][132] floats + xp [16][132] u64
    static const size_t FC_SMEM = (size_t)(128 * 132) * sizeof(float)
                                + (size_t)(16 * 132) * sizeof(u64);
    cudaFuncSetAttribute(k_fc, cudaFuncAttributeMaxDynamicSharedMemorySize,
                         (int)FC_SMEM);

    int nblk = (n + 31) / 32;
    k_fc<<<nblk, 128, FC_SMEM>>>(x, W, b, (const int*)nid, n);
    k_route<<<(n + 1) / 2, 256>>>(nid, out, n);
}